// round 11
// baseline (speedup 1.0000x reference)
#include <cuda_runtime.h>
#include <cuda_fp16.h>

// MKMMD loss, fused persistent kernel (R11 = R10 with fixed volatile read:
// half2 math + 2 CTAs/SM). 136 upper-tri 32x32 pair tiles x 2 D-halves
// (256 k) = 272 CTAs. Single-shot smem load, fp16 accum flushed per 64 k.
// Half-distances exchanged via L2 slab across the device barrier.
// total = concat(src,tgt): N=512 rows, D=512.
// result = (10*N + 2*sum_{i<j} s_i s_j (kL2+kL1)) / B^2, s=+/-1 by half.
// bw_x = 2*S_upper_x/(N^2-N)/100 ; k = sum_{m=0..4} exp(-d/(bw*10^m))

#define DDIM   512
#define NTIL   16
#define NTILES 136
#define GRID   272
#define KHALF  256        // k-values per CTA slice
#define SWH    132        // row stride in half2 units: 528B = 33*16B (odd)

__device__ float  g_p1[GRID];
__device__ float  g_p2[GRID];
__device__ float  g_p3[GRID];
__device__ float2 g_slab[2][NTILES][1024];   // [half][tile][pair] {l1,l2}
__device__ int    g_bar1;
__device__ int    g_bar2;

// block reduce; valid result on thread 0 only
__device__ __forceinline__ float bred(float v, float* sbuf) {
    const int tid = threadIdx.x;
#pragma unroll
    for (int o = 16; o; o >>= 1) v += __shfl_down_sync(0xffffffffu, v, o);
    __syncthreads();
    if ((tid & 31) == 0) sbuf[tid >> 5] = v;
    __syncthreads();
    float r = 0.0f;
    if (tid == 0) {
#pragma unroll
        for (int w = 0; w < 8; ++w) r += sbuf[w];
    }
    return r;
}

__device__ __forceinline__ unsigned pk(float x, float y) {
    __half2 h = __floats2half2_rn(x, y);
    return *reinterpret_cast<unsigned*>(&h);
}
__device__ __forceinline__ __half2 uph(unsigned u) {
    return *reinterpret_cast<__half2*>(&u);
}

__global__ __launch_bounds__(256, 2) void mkmmd_kernel(
    const float* __restrict__ src, const float* __restrict__ tgt,
    float* __restrict__ out)
{
    __shared__ __align__(16) unsigned As[32][SWH];   // half2 elements
    __shared__ __align__(16) unsigned Bs[32][SWH];
    __shared__ float sbuf[8];
    __shared__ float siv[10];
    __shared__ int   winflag;

    const int tid = threadIdx.x;
    const int tx = tid & 15;
    const int ty = tid >> 4;

    const int tile = blockIdx.x >> 1;
    const int half = blockIdx.x & 1;

    // decode upper-triangle tile (ti <= tj) over 16x16 grid of 32x32 tiles
    int t = tile, ti = 0;
    while (t >= NTIL - ti) { t -= NTIL - ti; ti++; }
    const int tj = ti + t;
    const int i0 = ti * 32, j0 = tj * 32;
    const float* Ap = (i0 < 256) ? src + (size_t)i0 * DDIM : tgt + (size_t)(i0 - 256) * DDIM;
    const float* Bp = (j0 < 256) ? src + (size_t)j0 * DDIM : tgt + (size_t)(j0 - 256) * DDIM;
    const int kb0 = half * KHALF;

    // ---- one-shot load: 32 rows x 256 k of A and B, fp32 -> half2 ----
    {
        const int lr = tid >> 3;             // row 0..31
        const int fc = (tid & 7) * 32;       // 32 floats per thread per row
        const int hc = (tid & 7) * 16;       // half2 offset in smem row
        const float* ar = Ap + (size_t)lr * DDIM + kb0 + fc;
        const float* br = Bp + (size_t)lr * DDIM + kb0 + fc;
#pragma unroll
        for (int m = 0; m < 4; ++m) {
            float4 x = ((const float4*)ar)[2 * m];
            float4 y = ((const float4*)ar)[2 * m + 1];
            uint4 ua = make_uint4(pk(x.x, x.y), pk(x.z, x.w),
                                  pk(y.x, y.y), pk(y.z, y.w));
            float4 u = ((const float4*)br)[2 * m];
            float4 v = ((const float4*)br)[2 * m + 1];
            uint4 ub = make_uint4(pk(u.x, u.y), pk(u.z, u.w),
                                  pk(v.x, v.y), pk(v.z, v.w));
            *(uint4*)&As[lr][hc + 4 * m] = ua;
            *(uint4*)&Bs[lr][hc + 4 * m] = ub;
        }
    }
    __syncthreads();

    // ---- mainloop: 32 q-groups (8 k each), flush fp16->fp32 every 8 q ----
    float l1a[2][2] = {{0.f, 0.f}, {0.f, 0.f}};
    float l2a[2][2] = {{0.f, 0.f}, {0.f, 0.f}};

    const uint4* a0p = (const uint4*)&As[ty][0];
    const uint4* a1p = (const uint4*)&As[ty + 16][0];
    const uint4* b0p = (const uint4*)&Bs[tx][0];
    const uint4* b1p = (const uint4*)&Bs[tx + 16][0];

    for (int g = 0; g < 4; ++g) {
        __half2 h1[2][2], h2[2][2];
        const __half2 hz = __float2half2_rn(0.0f);
#pragma unroll
        for (int u = 0; u < 2; ++u)
#pragma unroll
            for (int v = 0; v < 2; ++v) { h1[u][v] = hz; h2[u][v] = hz; }

#pragma unroll
        for (int qq = 0; qq < 8; ++qq) {
            const int q = g * 8 + qq;
            uint4 A0 = a0p[q], A1 = a1p[q], B0 = b0p[q], B1 = b1p[q];
            const unsigned au0[4] = {A0.x, A0.y, A0.z, A0.w};
            const unsigned au1[4] = {A1.x, A1.y, A1.z, A1.w};
            const unsigned bu0[4] = {B0.x, B0.y, B0.z, B0.w};
            const unsigned bu1[4] = {B1.x, B1.y, B1.z, B1.w};
#pragma unroll
            for (int h = 0; h < 4; ++h) {
                __half2 av[2] = {uph(au0[h]), uph(au1[h])};
                __half2 bv[2] = {uph(bu0[h]), uph(bu1[h])};
#pragma unroll
                for (int u = 0; u < 2; ++u)
#pragma unroll
                    for (int v = 0; v < 2; ++v) {
                        __half2 d = __hsub2(av[u], bv[v]);        // HADD2 (fma)
                        h1[u][v] = __hadd2(h1[u][v], __habs2(d)); // LOP3 + HADD2
                        h2[u][v] = __hfma2(d, d, h2[u][v]);       // HFMA2 (fma)
                    }
            }
        }

#pragma unroll
        for (int u = 0; u < 2; ++u)
#pragma unroll
            for (int v = 0; v < 2; ++v) {
                float2 f1 = __half22float2(h1[u][v]);
                float2 f2 = __half22float2(h2[u][v]);
                l1a[u][v] += f1.x + f1.y;
                l2a[u][v] += f2.x + f2.y;
            }
    }

    // ---- slab write + masked partial sums for bandwidth ----
    float s1 = 0.0f, s2 = 0.0f;
#pragma unroll
    for (int u = 0; u < 2; ++u) {
        const int il = ty + 16 * u;
#pragma unroll
        for (int v = 0; v < 2; ++v) {
            const int jl = tx + 16 * v;
            g_slab[half][tile][il * 32 + jl] = make_float2(l1a[u][v], l2a[u][v]);
            if (ti < tj || jl > il) { s1 += l1a[u][v]; s2 += l2a[u][v]; }
        }
    }

    {
        float r1 = bred(s1, sbuf);
        float r2 = bred(s2, sbuf);
        if (tid == 0) {
            g_p1[blockIdx.x] = r1;
            g_p2[blockIdx.x] = r2;
            __threadfence();
            atomicAdd(&g_bar1, 1);
            while (*(volatile int*)&g_bar1 < GRID) {}
            __threadfence();
        }
        __syncthreads();   // release whole CTA; all slabs + partials visible
    }

    // ---- bandwidth ladder from 272 partials (fixed order, deterministic) ----
    {
        float v1 = ((volatile float*)g_p1)[tid];
        float v2 = ((volatile float*)g_p2)[tid];
        if (tid < GRID - 256) {
            v1 += ((volatile float*)g_p1)[tid + 256];
            v2 += ((volatile float*)g_p2)[tid + 256];
        }
        float S1 = bred(v1, sbuf);
        float S2 = bred(v2, sbuf);
        if (tid == 0) {
            const float cc = 2.0f * 0.01f / 261632.0f;   // 2/(N^2-N)/100
            float iv1 = 1.0f / (S1 * cc);
            float iv2 = 1.0f / (S2 * cc);
#pragma unroll
            for (int m = 0; m < 5; ++m) {
                siv[m]     = iv1;
                siv[5 + m] = iv2;
                iv1 *= 0.1f;
                iv2 *= 0.1f;
            }
        }
        __syncthreads();
    }

    // ---- exp phase: this CTA handles row-half u == half of its tile ----
    float acc = 0.0f;
    {
        const int u = half;
        const int il = ty + 16 * u;
#pragma unroll
        for (int v = 0; v < 2; ++v) {
            const int jl = tx + 16 * v;
            if (ti < tj || jl > il) {
                const volatile float* op =
                    (const volatile float*)&g_slab[1 - half][tile][il * 32 + jl];
                float l1 = l1a[u][v] + op[0];
                float l2 = l2a[u][v] + op[1];
                float kv = 0.0f;
#pragma unroll
                for (int m = 0; m < 5; ++m) {
                    kv += __expf(-l1 * siv[m]);
                    kv += __expf(-l2 * siv[5 + m]);
                }
                acc += kv;
            }
        }
    }

    float atot = bred(acc, sbuf);
    if (tid == 0) {
        const float sgn = ((ti < 8) == (tj < 8)) ? 1.0f : -1.0f;
        g_p3[blockIdx.x] = sgn * atot;
        __threadfence();
        int r = atomicAdd(&g_bar2, 1);
        winflag = (r == GRID - 1);
    }
    __syncthreads();

    if (winflag) {
        // last-arriving CTA: everyone is past bar1 -> safe to finalize + reset
        float v = ((volatile float*)g_p3)[tid];
        if (tid < GRID - 256) v += ((volatile float*)g_p3)[tid + 256];
        float s = bred(v, sbuf);
        if (tid == 0) {
            out[0] = 5120.0f / 65536.0f + s * (2.0f / 65536.0f);
            g_bar1 = 0;
            g_bar2 = 0;
            __threadfence();
        }
    }
}

extern "C" void kernel_launch(void* const* d_in, const int* in_sizes, int n_in,
                              void* d_out, int out_size) {
    const float* src = (const float*)d_in[0];
    const float* tgt = (const float*)d_in[1];
    float* out = (float*)d_out;
    mkmmd_kernel<<<GRID, 256>>>(src, tgt, out);
}

// round 12
// speedup vs baseline: 1.0935x; 1.0935x over previous
#include <cuda_runtime.h>
#include <cuda_fp16.h>

// MKMMD loss, fused persistent kernel (R12 = R9 skeleton + CH=128 (4 syncs)
// + fused pair reductions). 136 CTAs, one 32x32 pair tile each, full D=512,
// half2 math, fp16 accум flushed to fp32 every 64 k, distances register-
// resident across the device barrier, exp from registers.
// total = concat(src,tgt): N=512 rows, D=512.
// result = (10*N + 2*sum_{i<j} s_i s_j (kL2+kL1)) / B^2, s=+/-1 by half.
// bw_x = 2*S_upper_x/(N^2-N)/100 ; k = sum_{m=0..4} exp(-d/(bw*10^m))

#define DDIM  512
#define NTIL  16
#define GRID  136
#define CH    128         // k-values per smem chunk (2 fp16 flush groups)
#define SWH   68          // row stride in half2 units: 272B = 17*16B (odd)
                          // -> 16B-aligned rows, conflict-free LDS.128

__device__ float g_p1[GRID];
__device__ float g_p2[GRID];
__device__ float g_p3[GRID];
__device__ int   g_bar1;
__device__ int   g_bar2;

// fused block reduce of two floats; valid on thread 0 only
__device__ __forceinline__ void bred2(float& x, float& y, float* sbuf) {
    const int tid = threadIdx.x;
#pragma unroll
    for (int o = 16; o; o >>= 1) {
        x += __shfl_down_sync(0xffffffffu, x, o);
        y += __shfl_down_sync(0xffffffffu, y, o);
    }
    __syncthreads();                 // protect sbuf reuse across calls
    if ((tid & 31) == 0) {
        sbuf[2 * (tid >> 5)]     = x;
        sbuf[2 * (tid >> 5) + 1] = y;
    }
    __syncthreads();
    if (tid == 0) {
        float rx = 0.0f, ry = 0.0f;
#pragma unroll
        for (int w = 0; w < 8; ++w) { rx += sbuf[2 * w]; ry += sbuf[2 * w + 1]; }
        x = rx; y = ry;
    }
}

// single-value block reduce; valid on thread 0 only
__device__ __forceinline__ float bred(float v, float* sbuf) {
    const int tid = threadIdx.x;
#pragma unroll
    for (int o = 16; o; o >>= 1) v += __shfl_down_sync(0xffffffffu, v, o);
    __syncthreads();
    if ((tid & 31) == 0) sbuf[tid >> 5] = v;
    __syncthreads();
    float r = 0.0f;
    if (tid == 0) {
#pragma unroll
        for (int w = 0; w < 8; ++w) r += sbuf[w];
    }
    return r;
}

__device__ __forceinline__ unsigned pk(float x, float y) {
    __half2 h = __floats2half2_rn(x, y);
    return *reinterpret_cast<unsigned*>(&h);
}
__device__ __forceinline__ __half2 uph(unsigned u) {
    return *reinterpret_cast<__half2*>(&u);
}

__global__ __launch_bounds__(256, 1) void mkmmd_kernel(
    const float* __restrict__ src, const float* __restrict__ tgt,
    float* __restrict__ out)
{
    __shared__ __align__(16) unsigned As[2][32][SWH];   // half2 elements
    __shared__ __align__(16) unsigned Bs[2][32][SWH];
    __shared__ float sbuf[16];
    __shared__ float siv[10];
    __shared__ int   winflag;

    const int tid = threadIdx.x;
    const int tx = tid & 15;
    const int ty = tid >> 4;

    // decode upper-triangle tile (ti <= tj) over 16x16 grid of 32x32 tiles
    int t = blockIdx.x, ti = 0;
    while (t >= NTIL - ti) { t -= NTIL - ti; ti++; }
    const int tj = ti + t;
    const int i0 = ti * 32, j0 = tj * 32;
    const float* Ap = (i0 < 256) ? src + (size_t)i0 * DDIM : tgt + (size_t)(i0 - 256) * DDIM;
    const float* Bp = (j0 < 256) ? src + (size_t)j0 * DDIM : tgt + (size_t)(j0 - 256) * DDIM;

    // load assignment: row lr (0..31), 16 floats (-> 8 half2) at lcf
    const int lr  = tid >> 3;
    const int lcf = (tid & 7) * 16;       // float offset within 128-wide chunk
    const int lch = (tid & 7) * 8;        // half2 offset in smem row

    float l1a[2][2] = {{0.f, 0.f}, {0.f, 0.f}};
    float l2a[2][2] = {{0.f, 0.f}, {0.f, 0.f}};

    float4 pa[4], pb[4];
#pragma unroll
    for (int m = 0; m < 4; ++m) {
        pa[m] = ((const float4*)(Ap + (size_t)lr * DDIM + lcf))[m];
        pb[m] = ((const float4*)(Bp + (size_t)lr * DDIM + lcf))[m];
    }

    const int NCHUNK = DDIM / CH;   // 4
    for (int c = 0; c < NCHUNK; ++c) {
        const int p = c & 1;
        // convert prefetched floats to half2; two STS.128 per matrix
        {
            uint4 ua0 = make_uint4(pk(pa[0].x, pa[0].y), pk(pa[0].z, pa[0].w),
                                   pk(pa[1].x, pa[1].y), pk(pa[1].z, pa[1].w));
            uint4 ua1 = make_uint4(pk(pa[2].x, pa[2].y), pk(pa[2].z, pa[2].w),
                                   pk(pa[3].x, pa[3].y), pk(pa[3].z, pa[3].w));
            uint4 ub0 = make_uint4(pk(pb[0].x, pb[0].y), pk(pb[0].z, pb[0].w),
                                   pk(pb[1].x, pb[1].y), pk(pb[1].z, pb[1].w));
            uint4 ub1 = make_uint4(pk(pb[2].x, pb[2].y), pk(pb[2].z, pb[2].w),
                                   pk(pb[3].x, pb[3].y), pk(pb[3].z, pb[3].w));
            *(uint4*)&As[p][lr][lch]     = ua0;
            *(uint4*)&As[p][lr][lch + 4] = ua1;
            *(uint4*)&Bs[p][lr][lch]     = ub0;
            *(uint4*)&Bs[p][lr][lch + 4] = ub1;
        }
        __syncthreads();   // also guarantees compute(c-1) done before next STS

        if (c < NCHUNK - 1) {
            const int kb = (c + 1) * CH;
#pragma unroll
            for (int m = 0; m < 4; ++m) {
                pa[m] = ((const float4*)(Ap + (size_t)lr * DDIM + kb + lcf))[m];
                pb[m] = ((const float4*)(Bp + (size_t)lr * DDIM + kb + lcf))[m];
            }
        }

        const uint4* a0p = (const uint4*)&As[p][ty][0];
        const uint4* a1p = (const uint4*)&As[p][ty + 16][0];
        const uint4* b0p = (const uint4*)&Bs[p][tx][0];
        const uint4* b1p = (const uint4*)&Bs[p][tx + 16][0];

        // two fp16 accumulation groups of 64 k each (validated chain length)
#pragma unroll
        for (int g = 0; g < 2; ++g) {
            __half2 h1[2][2], h2[2][2];
            const __half2 hz = __float2half2_rn(0.0f);
#pragma unroll
            for (int u = 0; u < 2; ++u)
#pragma unroll
                for (int v = 0; v < 2; ++v) { h1[u][v] = hz; h2[u][v] = hz; }

#pragma unroll
            for (int qq = 0; qq < 8; ++qq) {   // 8 k per q via LDS.128
                const int q = g * 8 + qq;
                uint4 A0 = a0p[q], A1 = a1p[q], B0 = b0p[q], B1 = b1p[q];
                const unsigned au0[4] = {A0.x, A0.y, A0.z, A0.w};
                const unsigned au1[4] = {A1.x, A1.y, A1.z, A1.w};
                const unsigned bu0[4] = {B0.x, B0.y, B0.z, B0.w};
                const unsigned bu1[4] = {B1.x, B1.y, B1.z, B1.w};
#pragma unroll
                for (int h = 0; h < 4; ++h) {
                    __half2 av[2] = {uph(au0[h]), uph(au1[h])};
                    __half2 bv[2] = {uph(bu0[h]), uph(bu1[h])};
#pragma unroll
                    for (int u = 0; u < 2; ++u)
#pragma unroll
                        for (int v = 0; v < 2; ++v) {
                            __half2 d = __hsub2(av[u], bv[v]);        // fma pipe
                            h1[u][v] = __hadd2(h1[u][v], __habs2(d)); // |mod| fold
                            h2[u][v] = __hfma2(d, d, h2[u][v]);       // fma pipe
                        }
                }
            }

#pragma unroll
            for (int u = 0; u < 2; ++u)
#pragma unroll
                for (int v = 0; v < 2; ++v) {
                    float2 f1 = __half22float2(h1[u][v]);
                    float2 f2 = __half22float2(h2[u][v]);
                    l1a[u][v] += f1.x + f1.y;
                    l2a[u][v] += f2.x + f2.y;
                }
        }
    }

    // masked upper-triangle partial sums for bandwidth (dist stay in regs)
    bool keep[2][2];
    float s1 = 0.0f, s2 = 0.0f;
#pragma unroll
    for (int u = 0; u < 2; ++u)
#pragma unroll
        for (int v = 0; v < 2; ++v) {
            const int i = i0 + ty + 16 * u;
            const int j = j0 + tx + 16 * v;
            keep[u][v] = (ti < tj) || (j > i);
            if (keep[u][v]) { s1 += l1a[u][v]; s2 += l2a[u][v]; }
        }

    {
        bred2(s1, s2, sbuf);
        if (tid == 0) {
            g_p1[blockIdx.x] = s1;
            g_p2[blockIdx.x] = s2;
            __threadfence();
            atomicAdd(&g_bar1, 1);
            while (*(volatile int*)&g_bar1 < GRID) {}
            __threadfence();
        }
        __syncthreads();   // release whole CTA; all partials visible
    }

    // bandwidth ladder from the 136 partials (fixed order -> deterministic)
    {
        float v1 = 0.0f, v2 = 0.0f;
        if (tid < GRID) {
            v1 = ((volatile float*)g_p1)[tid];
            v2 = ((volatile float*)g_p2)[tid];
        }
        bred2(v1, v2, sbuf);
        if (tid == 0) {
            const float cc = 2.0f * 0.01f / 261632.0f;   // 2/(N^2-N)/100
            float iv1 = 1.0f / (v1 * cc);
            float iv2 = 1.0f / (v2 * cc);
#pragma unroll
            for (int m = 0; m < 5; ++m) {
                siv[m]     = iv1;
                siv[5 + m] = iv2;
                iv1 *= 0.1f;
                iv2 *= 0.1f;
            }
        }
        __syncthreads();
    }

    // exp phase straight from registers
    float acc = 0.0f;
#pragma unroll
    for (int u = 0; u < 2; ++u)
#pragma unroll
        for (int v = 0; v < 2; ++v) {
            if (keep[u][v]) {
                float kv = 0.0f;
#pragma unroll
                for (int m = 0; m < 5; ++m) {
                    kv += __expf(-l1a[u][v] * siv[m]);
                    kv += __expf(-l2a[u][v] * siv[5 + m]);
                }
                acc += kv;
            }
        }

    float atot = bred(acc, sbuf);
    if (tid == 0) {
        const float sgn = ((ti < 8) == (tj < 8)) ? 1.0f : -1.0f;
        g_p3[blockIdx.x] = sgn * atot;
        __threadfence();
        int r = atomicAdd(&g_bar2, 1);
        winflag = (r == GRID - 1);
    }
    __syncthreads();

    if (winflag) {
        // last-arriving CTA: everyone is past bar1 -> safe to finalize + reset
        float v = (tid < GRID) ? ((volatile float*)g_p3)[tid] : 0.0f;
        float s = bred(v, sbuf);
        if (tid == 0) {
            out[0] = 5120.0f / 65536.0f + s * (2.0f / 65536.0f);
            g_bar1 = 0;
            g_bar2 = 0;
            __threadfence();
        }
    }
}

extern "C" void kernel_launch(void* const* d_in, const int* in_sizes, int n_in,
                              void* d_out, int out_size) {
    const float* src = (const float*)d_in[0];
    const float* tgt = (const float*)d_in[1];
    float* out = (float*)d_out;
    mkmmd_kernel<<<GRID, 256>>>(src, tgt, out);
}

// round 13
// speedup vs baseline: 1.1372x; 1.0399x over previous
#include <cuda_runtime.h>
#include <cuda_fp16.h>

// MKMMD loss, fused persistent kernel (R13 = R9 best-measured config +
// fused pair reductions + negated exp ladder). 136 CTAs, one 32x32 pair
// tile each, full D=512, half2 math, fp16 accum flushed to fp32 every 64 k,
// distances register-resident across the device barrier.
// total = concat(src,tgt): N=512 rows, D=512.
// result = (10*N + 2*sum_{i<j} s_i s_j (kL2+kL1)) / B^2, s=+/-1 by half.
// bw_x = 2*S_upper_x/(N^2-N)/100 ; k = sum_{m=0..4} exp(-d/(bw*10^m))

#define DDIM  512
#define NTIL  16
#define GRID  136
#define CH    64          // k-values per chunk (fp16 accum chain length)
#define SWH   36          // row stride in half2 units: 144B = 9*16B (odd) ->
                          // conflict-free LDS.128, 16B-aligned rows

__device__ float g_p1[GRID];
__device__ float g_p2[GRID];
__device__ float g_p3[GRID];
__device__ int   g_bar1;
__device__ int   g_bar2;

// fused block reduce of two floats; valid on thread 0 only
__device__ __forceinline__ void bred2(float& x, float& y, float* sbuf) {
    const int tid = threadIdx.x;
#pragma unroll
    for (int o = 16; o; o >>= 1) {
        x += __shfl_down_sync(0xffffffffu, x, o);
        y += __shfl_down_sync(0xffffffffu, y, o);
    }
    __syncthreads();                 // protect sbuf reuse across calls
    if ((tid & 31) == 0) {
        sbuf[2 * (tid >> 5)]     = x;
        sbuf[2 * (tid >> 5) + 1] = y;
    }
    __syncthreads();
    if (tid == 0) {
        float rx = 0.0f, ry = 0.0f;
#pragma unroll
        for (int w = 0; w < 8; ++w) { rx += sbuf[2 * w]; ry += sbuf[2 * w + 1]; }
        x = rx; y = ry;
    }
}

// single-value block reduce; valid on thread 0 only
__device__ __forceinline__ float bred(float v, float* sbuf) {
    const int tid = threadIdx.x;
#pragma unroll
    for (int o = 16; o; o >>= 1) v += __shfl_down_sync(0xffffffffu, v, o);
    __syncthreads();
    if ((tid & 31) == 0) sbuf[tid >> 5] = v;
    __syncthreads();
    float r = 0.0f;
    if (tid == 0) {
#pragma unroll
        for (int w = 0; w < 8; ++w) r += sbuf[w];
    }
    return r;
}

__device__ __forceinline__ unsigned pk(float x, float y) {
    __half2 h = __floats2half2_rn(x, y);
    return *reinterpret_cast<unsigned*>(&h);
}
__device__ __forceinline__ __half2 uph(unsigned u) {
    return *reinterpret_cast<__half2*>(&u);
}

__global__ __launch_bounds__(256, 1) void mkmmd_kernel(
    const float* __restrict__ src, const float* __restrict__ tgt,
    float* __restrict__ out)
{
    __shared__ __align__(16) unsigned As[2][32][SWH];   // half2 elements
    __shared__ __align__(16) unsigned Bs[2][32][SWH];
    __shared__ float sbuf[16];
    __shared__ float siv[10];       // NEGATED inverse-bandwidth ladders
    __shared__ int   winflag;

    const int tid = threadIdx.x;
    const int tx = tid & 15;
    const int ty = tid >> 4;

    // decode upper-triangle tile (ti <= tj) over 16x16 grid of 32x32 tiles
    int t = blockIdx.x, ti = 0;
    while (t >= NTIL - ti) { t -= NTIL - ti; ti++; }
    const int tj = ti + t;
    const int i0 = ti * 32, j0 = tj * 32;
    const float* Ap = (i0 < 256) ? src + (size_t)i0 * DDIM : tgt + (size_t)(i0 - 256) * DDIM;
    const float* Bp = (j0 < 256) ? src + (size_t)j0 * DDIM : tgt + (size_t)(j0 - 256) * DDIM;

    // load assignment: row lr (0..31), 8 floats (-> 4 half2) at lcf
    const int lr  = tid >> 3;
    const int lcf = (tid & 7) * 8;        // float offset within 64-wide chunk
    const int lch = (tid & 7) * 4;        // half2 offset in smem row

    float l1a[2][2] = {{0.f, 0.f}, {0.f, 0.f}};
    float l2a[2][2] = {{0.f, 0.f}, {0.f, 0.f}};

    float4 pa0 = *(const float4*)(Ap + (size_t)lr * DDIM + lcf);
    float4 pa1 = *(const float4*)(Ap + (size_t)lr * DDIM + lcf + 4);
    float4 pb0 = *(const float4*)(Bp + (size_t)lr * DDIM + lcf);
    float4 pb1 = *(const float4*)(Bp + (size_t)lr * DDIM + lcf + 4);

    const int NCHUNK = DDIM / CH;   // 8
    for (int c = 0; c < NCHUNK; ++c) {
        const int p = c & 1;
        // convert prefetched floats to half2, one STS.128 per matrix
        {
            uint4 ua = make_uint4(pk(pa0.x, pa0.y), pk(pa0.z, pa0.w),
                                  pk(pa1.x, pa1.y), pk(pa1.z, pa1.w));
            uint4 ub = make_uint4(pk(pb0.x, pb0.y), pk(pb0.z, pb0.w),
                                  pk(pb1.x, pb1.y), pk(pb1.z, pb1.w));
            *(uint4*)&As[p][lr][lch] = ua;
            *(uint4*)&Bs[p][lr][lch] = ub;
        }
        __syncthreads();   // also guarantees compute(c-1) done before next STS

        if (c < NCHUNK - 1) {
            const int kb = (c + 1) * CH;
            pa0 = *(const float4*)(Ap + (size_t)lr * DDIM + kb + lcf);
            pa1 = *(const float4*)(Ap + (size_t)lr * DDIM + kb + lcf + 4);
            pb0 = *(const float4*)(Bp + (size_t)lr * DDIM + kb + lcf);
            pb1 = *(const float4*)(Bp + (size_t)lr * DDIM + kb + lcf + 4);
        }

        // fp16 chunk accumulators (chain length 64 adds, values << 65504)
        __half2 h1[2][2], h2[2][2];
        const __half2 hz = __float2half2_rn(0.0f);
#pragma unroll
        for (int u = 0; u < 2; ++u)
#pragma unroll
            for (int v = 0; v < 2; ++v) { h1[u][v] = hz; h2[u][v] = hz; }

        const uint4* a0p = (const uint4*)&As[p][ty][0];
        const uint4* a1p = (const uint4*)&As[p][ty + 16][0];
        const uint4* b0p = (const uint4*)&Bs[p][tx][0];
        const uint4* b1p = (const uint4*)&Bs[p][tx + 16][0];

#pragma unroll
        for (int q = 0; q < CH / 8; ++q) {     // 8 k per q via LDS.128
            uint4 A0 = a0p[q], A1 = a1p[q], B0 = b0p[q], B1 = b1p[q];
            const unsigned au0[4] = {A0.x, A0.y, A0.z, A0.w};
            const unsigned au1[4] = {A1.x, A1.y, A1.z, A1.w};
            const unsigned bu0[4] = {B0.x, B0.y, B0.z, B0.w};
            const unsigned bu1[4] = {B1.x, B1.y, B1.z, B1.w};
#pragma unroll
            for (int h = 0; h < 4; ++h) {      // 2 k per h
                __half2 av[2] = {uph(au0[h]), uph(au1[h])};
                __half2 bv[2] = {uph(bu0[h]), uph(bu1[h])};
#pragma unroll
                for (int u = 0; u < 2; ++u)
#pragma unroll
                    for (int v = 0; v < 2; ++v) {
                        __half2 d = __hsub2(av[u], bv[v]);        // HADD2 (fma)
                        h1[u][v] = __hadd2(h1[u][v], __habs2(d)); // LOP3 + HADD2
                        h2[u][v] = __hfma2(d, d, h2[u][v]);       // HFMA2 (fma)
                    }
            }
        }

        // flush chunk accumulators to fp32
#pragma unroll
        for (int u = 0; u < 2; ++u)
#pragma unroll
            for (int v = 0; v < 2; ++v) {
                float2 f1 = __half22float2(h1[u][v]);
                float2 f2 = __half22float2(h2[u][v]);
                l1a[u][v] += f1.x + f1.y;
                l2a[u][v] += f2.x + f2.y;
            }
    }

    // masked upper-triangle partial sums for bandwidth (dist stay in regs)
    bool keep[2][2];
    float s1 = 0.0f, s2 = 0.0f;
#pragma unroll
    for (int u = 0; u < 2; ++u)
#pragma unroll
        for (int v = 0; v < 2; ++v) {
            const int i = i0 + ty + 16 * u;
            const int j = j0 + tx + 16 * v;
            keep[u][v] = (ti < tj) || (j > i);
            if (keep[u][v]) { s1 += l1a[u][v]; s2 += l2a[u][v]; }
        }

    {
        bred2(s1, s2, sbuf);
        if (tid == 0) {
            g_p1[blockIdx.x] = s1;
            g_p2[blockIdx.x] = s2;
            __threadfence();
            atomicAdd(&g_bar1, 1);
            while (*(volatile int*)&g_bar1 < GRID) {}
            __threadfence();
        }
        __syncthreads();   // release whole CTA; all partials visible
    }

    // bandwidth ladder from the 136 partials (fixed order -> deterministic)
    {
        float v1 = 0.0f, v2 = 0.0f;
        if (tid < GRID) {
            v1 = ((volatile float*)g_p1)[tid];
            v2 = ((volatile float*)g_p2)[tid];
        }
        bred2(v1, v2, sbuf);
        if (tid == 0) {
            const float cc = 2.0f * 0.01f / 261632.0f;   // 2/(N^2-N)/100
            float iv1 = -1.0f / (v1 * cc);               // negated ladder
            float iv2 = -1.0f / (v2 * cc);
#pragma unroll
            for (int m = 0; m < 5; ++m) {
                siv[m]     = iv1;
                siv[5 + m] = iv2;
                iv1 *= 0.1f;
                iv2 *= 0.1f;
            }
        }
        __syncthreads();
    }

    // exp phase straight from registers (scales pre-negated)
    float acc = 0.0f;
#pragma unroll
    for (int u = 0; u < 2; ++u)
#pragma unroll
        for (int v = 0; v < 2; ++v) {
            if (keep[u][v]) {
                float kv = 0.0f;
#pragma unroll
                for (int m = 0; m < 5; ++m) {
                    kv += __expf(l1a[u][v] * siv[m]);
                    kv += __expf(l2a[u][v] * siv[5 + m]);
                }
                acc += kv;
            }
        }

    float atot = bred(acc, sbuf);
    if (tid == 0) {
        const float sgn = ((ti < 8) == (tj < 8)) ? 1.0f : -1.0f;
        g_p3[blockIdx.x] = sgn * atot;
        __threadfence();
        int r = atomicAdd(&g_bar2, 1);
        winflag = (r == GRID - 1);
    }
    __syncthreads();

    if (winflag) {
        // last-arriving CTA: everyone is past bar1 -> safe to finalize + reset
        float v = (tid < GRID) ? ((volatile float*)g_p3)[tid] : 0.0f;
        float s = bred(v, sbuf);
        if (tid == 0) {
            out[0] = 5120.0f / 65536.0f + s * (2.0f / 65536.0f);
            g_bar1 = 0;
            g_bar2 = 0;
            __threadfence();
        }
    }
}

extern "C" void kernel_launch(void* const* d_in, const int* in_sizes, int n_in,
                              void* d_out, int out_size) {
    const float* src = (const float*)d_in[0];
    const float* tgt = (const float*)d_in[1];
    float* out = (float*)d_out;
    mkmmd_kernel<<<GRID, 256>>>(src, tgt, out);
}